// round 3
// baseline (speedup 1.0000x reference)
#include <cuda_runtime.h>
#include <cuda_fp16.h>
#include <cstdint>

#define M_TOTAL 8192
#define N_TOTAL 11008
#define K_TOTAL 4096
#define GROUPS 32
#define PACKED 2048

#define BM 128
#define BN 128
#define BK 32
#define PAD 8

// Scratch: dequantized W (fp16) and converted x (fp16).
__device__ __half g_W[(size_t)N_TOTAL * K_TOTAL];  // ~90 MB
__device__ __half g_X[(size_t)M_TOTAL * K_TOTAL];  // ~67 MB

// ---------------------------------------------------------------------------
// Kernel 1: int4 grouped dequant -> fp16
// weight_packed[o][p] holds one byte: high nibble -> col 2p, low nibble -> col 2p+1
// ---------------------------------------------------------------------------
__global__ void dequant_kernel(const int* __restrict__ wp,
                               const float* __restrict__ scale,
                               const float* __restrict__ zp) {
    int idx = blockIdx.x * blockDim.x + threadIdx.x;
    if (idx >= N_TOTAL * PACKED) return;
    int o = idx >> 11;        // / 2048
    int p = idx & 2047;
    int v = wp[idx];
    int g = p >> 6;           // 64 packed entries per 128-wide group
    float s = __ldg(scale + o * GROUPS + g);
    float z = __ldg(zp + o * GROUPS + g);
    float hi = (float)((v >> 4) & 15);
    float lo = (float)(v & 15);
    // half2 element index = (o*4096 + 2p)/2 = o*2048 + p = idx
    reinterpret_cast<__half2*>(g_W)[idx] =
        __floats2half2_rn((hi - z) * s, (lo - z) * s);
}

// ---------------------------------------------------------------------------
// Kernel 2: x fp32 -> fp16 (vectorized float4)
// ---------------------------------------------------------------------------
__global__ void xconv_kernel(const float* __restrict__ x) {
    int i = blockIdx.x * blockDim.x + threadIdx.x;  // over float4 chunks
    float4 f = reinterpret_cast<const float4*>(x)[i];
    __half2* out = reinterpret_cast<__half2*>(g_X);
    out[2 * i]     = __floats2half2_rn(f.x, f.y);
    out[2 * i + 1] = __floats2half2_rn(f.z, f.w);
}

// ---------------------------------------------------------------------------
// Kernel 3: GEMM  out[m][n] = sum_k X[m][k] * W[n][k] + bias[n]
// 128x128x32 CTA tile, 8 warps (2 M x 4 N), warp tile 64x32,
// mma.sync m16n8k16 fp16->fp32, cp.async double buffering.
// ---------------------------------------------------------------------------
__global__ void __launch_bounds__(256, 2)
gemm_kernel(float* __restrict__ out, const float* __restrict__ bias) {
    __shared__ alignas(16) __half As[2][BM][BK + PAD];
    __shared__ alignas(16) __half Bs[2][BN][BK + PAD];

    const int tid  = threadIdx.x;
    const int lane = tid & 31;
    const int warp = tid >> 5;
    const int wm = (warp & 1) * 64;   // warp M offset inside CTA
    const int wn = (warp >> 1) * 32;  // warp N offset inside CTA

    const int m0 = blockIdx.y * BM;
    const int n0 = blockIdx.x * BN;

    const __half* Ag = g_X + (size_t)m0 * K_TOTAL;
    const __half* Bg = g_W + (size_t)n0 * K_TOTAL;

    float acc[4][4][4];
#pragma unroll
    for (int mi = 0; mi < 4; mi++)
#pragma unroll
        for (int ni = 0; ni < 4; ni++)
#pragma unroll
            for (int e = 0; e < 4; e++) acc[mi][ni][e] = 0.0f;

    auto load_stage = [&](int buf, int k0) {
#pragma unroll
        for (int i = tid; i < 512; i += 256) {
            int row = i >> 2;      // 0..127
            int seg = i & 3;       // 16B segment within 64B row chunk
            uint32_t da = (uint32_t)__cvta_generic_to_shared(&As[buf][row][seg * 8]);
            const __half* sa = Ag + (size_t)row * K_TOTAL + k0 + seg * 8;
            asm volatile("cp.async.cg.shared.global [%0], [%1], 16;\n"
                         :: "r"(da), "l"(sa));
            uint32_t db = (uint32_t)__cvta_generic_to_shared(&Bs[buf][row][seg * 8]);
            const __half* sb = Bg + (size_t)row * K_TOTAL + k0 + seg * 8;
            asm volatile("cp.async.cg.shared.global [%0], [%1], 16;\n"
                         :: "r"(db), "l"(sb));
        }
        asm volatile("cp.async.commit_group;\n");
    };

    load_stage(0, 0);

    const int r  = lane >> 2;        // 0..7 : fragment row / B n-index
    const int c2 = (lane & 3) * 2;   // 0,2,4,6 : fragment k-pair

    const int NK = K_TOTAL / BK;     // 128 iterations
    for (int kt = 0; kt < NK; kt++) {
        const int buf = kt & 1;
        if (kt + 1 < NK) {
            load_stage(buf ^ 1, (kt + 1) * BK);
            asm volatile("cp.async.wait_group 1;\n");
        } else {
            asm volatile("cp.async.wait_group 0;\n");
        }
        __syncthreads();

#pragma unroll
        for (int ks = 0; ks < BK; ks += 16) {
            uint32_t a[4][4];
#pragma unroll
            for (int mi = 0; mi < 4; mi++) {
                a[mi][0] = *(const uint32_t*)(&As[buf][wm + mi * 16 + r    ][ks + c2    ]);
                a[mi][1] = *(const uint32_t*)(&As[buf][wm + mi * 16 + r + 8][ks + c2    ]);
                a[mi][2] = *(const uint32_t*)(&As[buf][wm + mi * 16 + r    ][ks + c2 + 8]);
                a[mi][3] = *(const uint32_t*)(&As[buf][wm + mi * 16 + r + 8][ks + c2 + 8]);
            }
            uint32_t b[4][2];
#pragma unroll
            for (int ni = 0; ni < 4; ni++) {
                b[ni][0] = *(const uint32_t*)(&Bs[buf][wn + ni * 8 + r][ks + c2    ]);
                b[ni][1] = *(const uint32_t*)(&Bs[buf][wn + ni * 8 + r][ks + c2 + 8]);
            }
#pragma unroll
            for (int mi = 0; mi < 4; mi++)
#pragma unroll
                for (int ni = 0; ni < 4; ni++) {
                    asm volatile(
                        "mma.sync.aligned.m16n8k16.row.col.f32.f16.f16.f32 "
                        "{%0,%1,%2,%3}, {%4,%5,%6,%7}, {%8,%9}, {%0,%1,%2,%3};\n"
                        : "+f"(acc[mi][ni][0]), "+f"(acc[mi][ni][1]),
                          "+f"(acc[mi][ni][2]), "+f"(acc[mi][ni][3])
                        : "r"(a[mi][0]), "r"(a[mi][1]), "r"(a[mi][2]), "r"(a[mi][3]),
                          "r"(b[ni][0]), "r"(b[ni][1]));
                }
        }
        __syncthreads();
    }

    // Epilogue: add bias, store fp32
#pragma unroll
    for (int mi = 0; mi < 4; mi++) {
        const int row = m0 + wm + mi * 16 + r;
#pragma unroll
        for (int ni = 0; ni < 4; ni++) {
            const int col = n0 + wn + ni * 8 + c2;
            const float b0 = __ldg(bias + col);
            const float b1 = __ldg(bias + col + 1);
            float2 v0 = make_float2(acc[mi][ni][0] + b0, acc[mi][ni][1] + b1);
            float2 v1 = make_float2(acc[mi][ni][2] + b0, acc[mi][ni][3] + b1);
            *reinterpret_cast<float2*>(out + (size_t)row * N_TOTAL + col) = v0;
            *reinterpret_cast<float2*>(out + (size_t)(row + 8) * N_TOTAL + col) = v1;
        }
    }
}

// ---------------------------------------------------------------------------
// Launch
// ---------------------------------------------------------------------------
extern "C" void kernel_launch(void* const* d_in, const int* in_sizes, int n_in,
                              void* d_out, int out_size) {
    const float* x     = (const float*)d_in[0];
    const int*   wp    = (const int*)d_in[1];
    const float* scale = (const float*)d_in[2];
    const float* zp    = (const float*)d_in[3];
    const float* bias  = (const float*)d_in[4];
    float* out = (float*)d_out;

    dequant_kernel<<<(N_TOTAL * PACKED + 255) / 256, 256>>>(wp, scale, zp);
    xconv_kernel<<<(M_TOTAL * K_TOTAL / 4) / 256, 256>>>(x);

    dim3 grid(N_TOTAL / BN, M_TOTAL / BM);  // 86 x 64
    gemm_kernel<<<grid, 256>>>(out, bias);
}